// round 15
// baseline (speedup 1.0000x reference)
#include <cuda_runtime.h>
#include <cuda_bf16.h>
#include <math.h>

// LSTM: T=512, B=64, I=H=512.  out[t,b,h] = h_t.
// conv_a/conv_w: split-bf16 fragments (R8, unchanged).
// lstm_rec (768 thr): warps 0-15 = persistent HMMA recurrence (R13, proven);
//   warps 16-23 = independent-warp GEMM sub-unit (R15: 8 warps/unit, warp =
//   (mf, nf-half), W frags via __ldg, red.release completion, 8192/t target).

#define Tq 512
#define Bq 64
#define Hq 512
#define G4 2048
#define AF4 2097152u
#define WF2 262144u

typedef unsigned long long ull;

__device__ float g_xp[(size_t)Tq * G4 * Bq];        // x_proj scratch (no bias)
__device__ unsigned g_cnt[4 * 32];                  // per-group step counters
__device__ unsigned g_td[Tq];                       // per-t x_proj progress (8192 = done)
__device__ unsigned g_fin;                          // global finish counter
__device__ uint4 g_af[2 * AF4];                     // A frags hi|lo
__device__ uint2 g_wf[2 * WF2];                     // W_ih frags hi|lo
__device__ uint4 g_hf[2 * 8192];                    // h frags [par][hi|lo][bq][kc][lane]

__device__ __forceinline__ void cpa16(void* s, const void* g) {
    unsigned sa = (unsigned)__cvta_generic_to_shared(s);
    asm volatile("cp.async.cg.shared.global [%0], [%1], 16;" :: "r"(sa), "l"(g));
}
__device__ __forceinline__ void cpcommit() { asm volatile("cp.async.commit_group;"); }
template <int N> __device__ __forceinline__ void cpwait() {
    asm volatile("cp.async.wait_group %0;" :: "n"(N));
}
__device__ __forceinline__ float sigf(float x) {
    return __fdividef(1.f, 1.f + __expf(-x));
}
__device__ __forceinline__ float tanhx(float x) {
    return __fdividef(2.f, 1.f + __expf(-2.f * x)) - 1.f;
}
__device__ __forceinline__ void split2(float2 v, unsigned& hi, unsigned& lo) {
    __nv_bfloat16 hx = __float2bfloat16(v.x);
    __nv_bfloat16 hy = __float2bfloat16(v.y);
    __nv_bfloat16 lx = __float2bfloat16(v.x - __bfloat162float(hx));
    __nv_bfloat16 ly = __float2bfloat16(v.y - __bfloat162float(hy));
    hi = (unsigned)__bfloat16_as_ushort(hx) | ((unsigned)__bfloat16_as_ushort(hy) << 16);
    lo = (unsigned)__bfloat16_as_ushort(lx) | ((unsigned)__bfloat16_as_ushort(ly) << 16);
}
__device__ __forceinline__ void mma16816(float* c, uint4 a, unsigned b0, unsigned b1) {
    asm volatile(
        "mma.sync.aligned.m16n8k16.row.col.f32.bf16.bf16.f32 "
        "{%0,%1,%2,%3},{%4,%5,%6,%7},{%8,%9},{%0,%1,%2,%3};"
        : "+f"(c[0]), "+f"(c[1]), "+f"(c[2]), "+f"(c[3])
        : "r"(a.x), "r"(a.y), "r"(a.z), "r"(a.w), "r"(b0), "r"(b1));
}

__global__ __launch_bounds__(256) void conv_a(const float* __restrict__ x) {
    unsigned idx = blockIdx.x * 256 + threadIdx.x;
    int lane = idx & 31;
    int kc = (idx >> 5) & 31;
    int mf = idx >> 10;
    int gr = lane >> 2, tc = (lane & 3) * 2;
    const float* base = x + (size_t)(mf * 16 + gr) * 512 + kc * 16 + tc;
    float2 r0 = *(const float2*)(base);
    float2 r1 = *(const float2*)(base + 8);
    float2 r2 = *(const float2*)(base + 8 * 512);
    float2 r3 = *(const float2*)(base + 8 * 512 + 8);
    uint4 hi, lo;
    split2(r0, hi.x, lo.x);
    split2(r2, hi.y, lo.y);
    split2(r1, hi.z, lo.z);
    split2(r3, hi.w, lo.w);
    unsigned o = (mf * 32 + kc) * 32 + lane;
    g_af[o] = hi;
    g_af[o + AF4] = lo;
}

__global__ __launch_bounds__(256) void conv_w(const float* __restrict__ W) {
    unsigned idx = blockIdx.x * 256 + threadIdx.x;
    int lane = idx & 31;
    int kc = (idx >> 5) & 31;
    int nf = idx >> 10;
    int gr = lane >> 2, tc = (lane & 3) * 2;
    const float* base = W + (size_t)(nf * 8 + gr) * 512 + kc * 16 + tc;
    float2 r0 = *(const float2*)(base);
    float2 r1 = *(const float2*)(base + 8);
    uint2 hi, lo;
    split2(r0, hi.x, lo.x);
    split2(r1, hi.y, lo.y);
    unsigned o = (nf * 32 + kc) * 32 + lane;
    g_wf[o] = hi;
    g_wf[o + WF2] = lo;
}

// ---------------------------------------------------------------------------
// smem layout
// ---------------------------------------------------------------------------
#define OFF_WF_LO 65536
#define OFF_HF    131072
#define OFF_HF_LO 147456
#define OFF_PEX   163840      // [32 rows][68] f32 = 8704
#define OFF_HO    172544      // [16][16] f32 = 1024
#define OFF_HBL   173568      // [16][17] u32 = 1088
#define OFF_BS    174656      // 64 f32 = 256
#define REC_SMEM  174912

__global__ __launch_bounds__(768, 1) void lstm_rec(
    const float* __restrict__ Whh, const float* __restrict__ bih,
    const float* __restrict__ bhh, float* __restrict__ out)
{
    extern __shared__ __align__(16) char smc[];
    uint2* wfHI = (uint2*)(smc);
    uint2* wfLO = (uint2*)(smc + OFF_WF_LO);
    uint4* hfHI = (uint4*)(smc + OFF_HF);
    uint4* hfLO = (uint4*)(smc + OFF_HF_LO);
    float* pex = (float*)(smc + OFF_PEX);
    float* ho = (float*)(smc + OFF_HO);
    unsigned* hbl = (unsigned*)(smc + OFF_HBL);
    float* bsm = (float*)(smc + OFF_BS);

    const int tid = threadIdx.x;
    const int bq = blockIdx.x >> 5;
    const int hg = blockIdx.x & 31;
    const int b0 = bq * 16;
    const int hc0 = hg * 16;
    unsigned* cnt = &g_cnt[bq * 32];

    if (tid < 512) {
        // ================= recurrence warps (0..15) — R13, proven =========
        const int warp = tid >> 5;
        const int lane = tid & 31;
        const int eb = tid & 15;
        const int ehcl = (tid >> 4) & 15;
        const int nf = warp & 7;
        const int kh = warp >> 3;

        for (int idx = tid; idx < 8192; idx += 512) {
            int l = idx & 31, nfi = (idx >> 5) & 7, kc = idx >> 8;
            int gr = l >> 2, tc2 = (l & 3) * 2;
            int c = nfi * 8 + gr;
            int grow = (c & 3) * 512 + hc0 + (c >> 2);
            const float* wb = Whh + (size_t)grow * 512 + kc * 16 + tc2;
            float2 r0 = *(const float2*)wb;
            float2 r1 = *(const float2*)(wb + 8);
            unsigned h0, l0, h1, l1;
            split2(r0, h0, l0);
            split2(r1, h1, l1);
            wfHI[(kc * 8 + nfi) * 32 + l] = make_uint2(h0, h1);
            wfLO[(kc * 8 + nfi) * 32 + l] = make_uint2(l0, l1);
        }
        if (tid < 64)
            bsm[tid] = bih[(tid & 3) * 512 + hc0 + (tid >> 2)]
                     + bhh[(tid & 3) * 512 + hc0 + (tid >> 2)];
        asm volatile("bar.sync 7, 512;" ::: "memory");

        float cst = 0.f;

#pragma unroll 1
        for (int t = 0; t < Tq; t++) {
            if (tid == 0) {
                unsigned vt;
                asm volatile("ld.acquire.gpu.u32 %0, [%1];"
                             : "=r"(vt) : "l"(&g_td[t]) : "memory");
                if (t > 0) {
                    unsigned tgt = 32u * (unsigned)t;
                    unsigned v;
                    do {
                        asm volatile("ld.acquire.gpu.u32 %0, [%1];"
                                     : "=r"(v) : "l"(cnt) : "memory");
                    } while (v < tgt);
                }
                if (vt < 8192u) {
                    unsigned v;
                    do {
                        asm volatile("ld.acquire.gpu.u32 %0, [%1];"
                                     : "=r"(v) : "l"(&g_td[t]) : "memory");
                    } while (v < 8192u);
                }
            }
            asm volatile("bar.sync 7, 512;" ::: "memory");

            float xv0 = 0.f, xv1 = 0.f, xv2 = 0.f, xv3 = 0.f;
            if (tid < 256) {
                const float* xpt = g_xp + (size_t)t * (G4 * Bq)
                                 + (size_t)(hc0 + ehcl) * Bq + b0 + eb;
                xv0 = __ldcg(xpt + 0 * 512 * Bq);
                xv1 = __ldcg(xpt + 1 * 512 * Bq);
                xv2 = __ldcg(xpt + 2 * 512 * Bq);
                xv3 = __ldcg(xpt + 3 * 512 * Bq);
            }

            if (t > 0) {
                const char* gB = (const char*)g_hf + (size_t)(t & 1) * 131072
                               + bq * 16384 + kh * 8192;
                char* sH = (char*)hfHI + kh * 8192;
                char* sL = (char*)hfLO + kh * 8192;
                int l = tid & 255;
                cpa16(sH + l * 16, gB + l * 16);
                cpa16(sH + (l + 256) * 16, gB + (l + 256) * 16);
                cpa16(sL + l * 16, gB + 65536 + l * 16);
                cpa16(sL + (l + 256) * 16, gB + 65536 + (l + 256) * 16);
                cpcommit();
                cpwait<0>();
                asm volatile("bar.sync %0, 256;" :: "r"(1 + kh) : "memory");

                float cc[4] = { 0.f, 0.f, 0.f, 0.f };
#pragma unroll 4
                for (int kc16 = 0; kc16 < 16; kc16++) {
                    int kc = kh * 16 + kc16;
                    uint4 ah = hfHI[kc * 32 + lane];
                    uint4 al = hfLO[kc * 32 + lane];
                    uint2 wh = wfHI[(kc * 8 + nf) * 32 + lane];
                    uint2 wl = wfLO[(kc * 8 + nf) * 32 + lane];
                    mma16816(cc, ah, wh.x, wh.y);
                    mma16816(cc, al, wh.x, wh.y);
                    mma16816(cc, ah, wl.x, wl.y);
                }
                {
                    int gr = lane >> 2, tc2 = (lane & 3) * 2;
                    int col = nf * 8 + tc2;
                    *(float2*)&pex[(kh * 16 + gr) * 68 + col] = make_float2(cc[0], cc[1]);
                    *(float2*)&pex[(kh * 16 + gr + 8) * 68 + col] = make_float2(cc[2], cc[3]);
                }
                asm volatile("bar.sync 7, 512;" ::: "memory");
            }

            if (tid < 256) {
                float g0 = xv0 + bsm[ehcl * 4 + 0];
                float g1 = xv1 + bsm[ehcl * 4 + 1];
                float g2 = xv2 + bsm[ehcl * 4 + 2];
                float g3 = xv3 + bsm[ehcl * 4 + 3];
                if (t > 0) {
                    float4 p0 = *(const float4*)&pex[eb * 68 + ehcl * 4];
                    float4 p1 = *(const float4*)&pex[(16 + eb) * 68 + ehcl * 4];
                    g0 += p0.x + p1.x;
                    g1 += p0.y + p1.y;
                    g2 += p0.z + p1.z;
                    g3 += p0.w + p1.w;
                }
                float iv = sigf(g0);
                float fv = sigf(g1);
                float gv = tanhx(g2);
                float ov = sigf(g3);
                cst = fv * cst + iv * gv;
                float hv = ov * tanhx(cst);

                ho[eb * 16 + ehcl] = hv;
                {
                    __nv_bfloat16 hh = __float2bfloat16(hv);
                    __nv_bfloat16 hl = __float2bfloat16(hv - __bfloat162float(hh));
                    hbl[ehcl * 17 + eb] = (unsigned)__bfloat16_as_ushort(hh)
                                        | ((unsigned)__bfloat16_as_ushort(hl) << 16);
                }
                asm volatile("bar.sync 10, 256;" ::: "memory");

                if (tid < 32) {
                    if (t < Tq - 1) {
                        int gr = lane >> 2;
                        int k0 = (lane & 3) * 2;
                        unsigned x0 = hbl[k0 * 17 + gr],        x1 = hbl[(k0 + 1) * 17 + gr];
                        unsigned y0 = hbl[k0 * 17 + gr + 8],    y1 = hbl[(k0 + 1) * 17 + gr + 8];
                        unsigned z0 = hbl[(k0 + 8) * 17 + gr],  z1 = hbl[(k0 + 9) * 17 + gr];
                        unsigned w0 = hbl[(k0 + 8) * 17 + gr + 8], w1 = hbl[(k0 + 9) * 17 + gr + 8];
                        uint4 hi = make_uint4(__byte_perm(x0, x1, 0x5410),
                                              __byte_perm(y0, y1, 0x5410),
                                              __byte_perm(z0, z1, 0x5410),
                                              __byte_perm(w0, w1, 0x5410));
                        uint4 lo = make_uint4(__byte_perm(x0, x1, 0x7632),
                                              __byte_perm(y0, y1, 0x7632),
                                              __byte_perm(z0, z1, 0x7632),
                                              __byte_perm(w0, w1, 0x7632));
                        size_t base = (size_t)((t + 1) & 1) * 8192 + (bq * 32 + hg) * 32 + lane;
                        g_hf[base] = hi;
                        g_hf[base + 4096] = lo;
                        __syncwarp();
                        if (lane == 0) {
                            unsigned old;
                            asm volatile("atom.release.gpu.add.u32 %0, [%1], 1;"
                                         : "=r"(old) : "l"(cnt) : "memory");
                        }
                    }
                } else if (tid >= 64 && tid < 128) {
                    int row = (tid - 64) >> 2, f4 = (tid - 64) & 3;
                    float4 v = ((const float4*)(ho + row * 16))[f4];
                    *(float4*)&out[(size_t)t * (Bq * Hq) + (size_t)(b0 + row) * Hq
                                   + hc0 + f4 * 4] = v;
                }
            }
        }

        if (tid == 0) {
            unsigned old;
            asm volatile("atom.release.gpu.add.u32 %0, [%1], 1;"
                         : "=r"(old) : "l"(&g_fin) : "memory");
            if (old == 127u) {
                for (int i = 0; i < Tq; i++) ((volatile unsigned*)g_td)[i] = 0u;
                for (int i = 0; i < 4; i++) ((volatile unsigned*)g_cnt)[i * 32] = 0u;
                *((volatile unsigned*)&g_fin) = 0u;
            }
        }
    } else {
        // ========== GEMM sub-unit (warps 16..23) — independent warps ======
        // Warp wg = (mf = wg&3, nh = wg>>2): 4 nf fragments each, W via __ldg
        // (fixed ntH per unit -> slice L2/L1-resident). No smem, no barriers.
        const int wg = (tid >> 5) - 16;         // 0..7
        const int w = wg & 3;                   // mf selector
        const int nh = wg >> 2;                 // nf half
        const int lane = tid & 31;
        const int gr = lane >> 2, tc2 = (lane & 3) * 2;
        const int ntH = blockIdx.x & 31;        // fixed for this unit

#pragma unroll 1
        for (int j = blockIdx.x; j < Tq * 32; j += 128) {
            int t = j >> 5;

            float c[4][4];
#pragma unroll
            for (int i = 0; i < 4; i++)
#pragma unroll
                for (int q = 0; q < 4; q++) c[i][q] = 0.f;

            uint4 ah = g_af[((size_t)(t * 4 + w) * 32 + 0) * 32 + lane];
            uint4 al = g_af[((size_t)(t * 4 + w) * 32 + 0) * 32 + lane + AF4];

#pragma unroll 2
            for (int kc = 0; kc < 32; kc++) {
                uint4 ahn, aln;
                if (kc + 1 < 32) {
                    ahn = g_af[((size_t)(t * 4 + w) * 32 + kc + 1) * 32 + lane];
                    aln = g_af[((size_t)(t * 4 + w) * 32 + kc + 1) * 32 + lane + AF4];
                }
#pragma unroll
                for (int i = 0; i < 4; i++) {
                    int nfi = nh * 4 + i;
                    unsigned wo = ((ntH * 8 + nfi) * 32 + kc) * 32 + lane;
                    uint2 h = __ldg(&g_wf[wo]);
                    uint2 l = __ldg(&g_wf[wo + WF2]);
                    mma16816(c[i], ah, h.x, h.y);
                    mma16816(c[i], al, h.x, h.y);
                    mma16816(c[i], ah, l.x, l.y);
                }
                ah = ahn; al = aln;
            }

            // epilogue: scattered fp32 stores into g_xp[t][n][b]
#pragma unroll
            for (int i = 0; i < 4; i++) {
                int n = ntH * 64 + (nh * 4 + i) * 8 + tc2;
                float* p = g_xp + ((size_t)t * G4 + n) * Bq + 16 * w + gr;
                p[0] = c[i][0];
                p[64] = c[i][1];
                p[8] = c[i][2];
                p[72] = c[i][3];
            }
            // every lane releases its own stores: 32 tiles * 256 lanes = 8192
            asm volatile("red.release.gpu.global.add.u32 [%0], 1;"
                         :: "l"(&g_td[t]) : "memory");
        }
    }
}

extern "C" void kernel_launch(void* const* d_in, const int* in_sizes, int n_in,
                              void* d_out, int out_size) {
    const float* x   = (const float*)d_in[0];   // [512,64,512]
    const float* Wih = (const float*)d_in[1];   // [2048,512]
    const float* Whh = (const float*)d_in[2];   // [2048,512]
    const float* bih = (const float*)d_in[3];   // [2048]
    const float* bhh = (const float*)d_in[4];   // [2048]
    float* out = (float*)d_out;                 // [512,64,512]

    cudaFuncSetAttribute(lstm_rec, cudaFuncAttributeMaxDynamicSharedMemorySize, REC_SMEM);

    conv_a<<<8192, 256>>>(x);
    conv_w<<<1024, 256>>>(Wih);
    lstm_rec<<<128, 768, REC_SMEM>>>(Whh, bih, bhh, out);
}

// round 17
// speedup vs baseline: 1.2840x; 1.2840x over previous
#include <cuda_runtime.h>
#include <cuda_bf16.h>
#include <math.h>

// LSTM: T=512, B=64, I=H=512.  out[t,b,h] = h_t.
// Sequential split (proven R10 structure):
//   conv_a/conv_w: split-bf16 fragments (R8, unchanged).
//   gemm_tc: R8-proven mainloop + direct [t][b][n] epilogue (16KB smem).
//   lstm_rec: R13-proven persistent HMMA recurrence; red.release producer.

#define Tq 512
#define Bq 64
#define Hq 512
#define G4 2048
#define AF4 2097152u
#define WF2 262144u

typedef unsigned long long ull;

__device__ float g_xp[(size_t)Tq * Bq * G4];        // x_proj [t][b][n], no bias
__device__ unsigned g_cnt[4 * 32];                  // per-group step counters
__device__ unsigned g_fin;                          // global finish counter
__device__ uint4 g_af[2 * AF4];                     // A frags hi|lo
__device__ uint2 g_wf[2 * WF2];                     // W_ih frags hi|lo
__device__ uint4 g_hf[2 * 8192];                    // h frags [par][hi|lo][bq][kc][lane]

__device__ __forceinline__ void cpa16(void* s, const void* g) {
    unsigned sa = (unsigned)__cvta_generic_to_shared(s);
    asm volatile("cp.async.cg.shared.global [%0], [%1], 16;" :: "r"(sa), "l"(g));
}
__device__ __forceinline__ void cpcommit() { asm volatile("cp.async.commit_group;"); }
template <int N> __device__ __forceinline__ void cpwait() {
    asm volatile("cp.async.wait_group %0;" :: "n"(N));
}
__device__ __forceinline__ float sigf(float x) {
    return __fdividef(1.f, 1.f + __expf(-x));
}
__device__ __forceinline__ float tanhx(float x) {
    return __fdividef(2.f, 1.f + __expf(-2.f * x)) - 1.f;
}
__device__ __forceinline__ void split2(float2 v, unsigned& hi, unsigned& lo) {
    __nv_bfloat16 hx = __float2bfloat16(v.x);
    __nv_bfloat16 hy = __float2bfloat16(v.y);
    __nv_bfloat16 lx = __float2bfloat16(v.x - __bfloat162float(hx));
    __nv_bfloat16 ly = __float2bfloat16(v.y - __bfloat162float(hy));
    hi = (unsigned)__bfloat16_as_ushort(hx) | ((unsigned)__bfloat16_as_ushort(hy) << 16);
    lo = (unsigned)__bfloat16_as_ushort(lx) | ((unsigned)__bfloat16_as_ushort(ly) << 16);
}
__device__ __forceinline__ void mma16816(float* c, uint4 a, unsigned b0, unsigned b1) {
    asm volatile(
        "mma.sync.aligned.m16n8k16.row.col.f32.bf16.bf16.f32 "
        "{%0,%1,%2,%3},{%4,%5,%6,%7},{%8,%9},{%0,%1,%2,%3};"
        : "+f"(c[0]), "+f"(c[1]), "+f"(c[2]), "+f"(c[3])
        : "r"(a.x), "r"(a.y), "r"(a.z), "r"(a.w), "r"(b0), "r"(b1));
}

__global__ __launch_bounds__(256) void conv_a(const float* __restrict__ x) {
    unsigned idx = blockIdx.x * 256 + threadIdx.x;
    int lane = idx & 31;
    int kc = (idx >> 5) & 31;
    int mf = idx >> 10;
    int gr = lane >> 2, tc = (lane & 3) * 2;
    const float* base = x + (size_t)(mf * 16 + gr) * 512 + kc * 16 + tc;
    float2 r0 = *(const float2*)(base);
    float2 r1 = *(const float2*)(base + 8);
    float2 r2 = *(const float2*)(base + 8 * 512);
    float2 r3 = *(const float2*)(base + 8 * 512 + 8);
    uint4 hi, lo;
    split2(r0, hi.x, lo.x);
    split2(r2, hi.y, lo.y);
    split2(r1, hi.z, lo.z);
    split2(r3, hi.w, lo.w);
    unsigned o = (mf * 32 + kc) * 32 + lane;
    g_af[o] = hi;
    g_af[o + AF4] = lo;
}

__global__ __launch_bounds__(256) void conv_w(const float* __restrict__ W) {
    unsigned idx = blockIdx.x * 256 + threadIdx.x;
    int lane = idx & 31;
    int kc = (idx >> 5) & 31;
    int nf = idx >> 10;
    int gr = lane >> 2, tc = (lane & 3) * 2;
    const float* base = W + (size_t)(nf * 8 + gr) * 512 + kc * 16 + tc;
    float2 r0 = *(const float2*)(base);
    float2 r1 = *(const float2*)(base + 8);
    uint2 hi, lo;
    split2(r0, hi.x, lo.x);
    split2(r1, hi.y, lo.y);
    unsigned o = (nf * 32 + kc) * 32 + lane;
    g_wf[o] = hi;
    g_wf[o + WF2] = lo;
}

// ---------------------------------------------------------------------------
// gemm_tc: C = A * W^T (no bias; rec adds it). 8 warps; W double-buffered
// (2x8KB smem); direct [t][b][n] stores (no transpose pass).
// ---------------------------------------------------------------------------
#define GEMM_SMEM 16384

__global__ __launch_bounds__(256) void gemm_tc() {
    extern __shared__ __align__(16) char smx[];
    const int tid = threadIdx.x;
    const int warp = tid >> 5;
    const int lane = tid & 31;
    const int gr = lane >> 2, tc = (lane & 3) * 2;
    const int nt = blockIdx.x;
    const int mt = blockIdx.y;
    const int mf = mt * 8 + warp;

    float c[16][4];
#pragma unroll
    for (int nf = 0; nf < 16; nf++)
#pragma unroll
        for (int j = 0; j < 4; j++) c[nf][j] = 0.f;

    auto load_w = [&](int kc, int buf) {
        int nfg = nt * 16 + (tid >> 4);
        int l16 = tid & 15;
        const char* src = (const char*)g_wf + ((size_t)(nfg * 32 + kc) * 32) * 8 + l16 * 16;
        char* dst = smx + buf * 8192 + (tid >> 4) * 256 + l16 * 16;
        cpa16(dst, src);
        cpa16(dst + 4096, src + (size_t)WF2 * 8);
        cpcommit();
    };

    uint4 ah = g_af[(mf * 32 + 0) * 32 + lane];
    uint4 al = g_af[(mf * 32 + 0) * 32 + lane + AF4];
    load_w(0, 0);
    load_w(1, 1);

#pragma unroll 1
    for (int kc = 0; kc < 32; kc++) {
        if (kc < 31) cpwait<1>(); else cpwait<0>();
        __syncthreads();
        uint4 ahn, aln;
        if (kc + 1 < 32) {
            ahn = g_af[(mf * 32 + kc + 1) * 32 + lane];
            aln = g_af[(mf * 32 + kc + 1) * 32 + lane + AF4];
        }
        const uint2* wh = (const uint2*)(smx + (kc & 1) * 8192);
        const uint2* wl = (const uint2*)(smx + (kc & 1) * 8192 + 4096);
#pragma unroll
        for (int nf = 0; nf < 16; nf++) {
            uint2 h = wh[nf * 32 + lane];
            uint2 l = wl[nf * 32 + lane];
            mma16816(c[nf], ah, h.x, h.y);
            mma16816(c[nf], al, h.x, h.y);
            mma16816(c[nf], ah, l.x, l.y);
        }
        __syncthreads();
        if (kc + 2 < 32) load_w(kc + 2, kc & 1);
        ah = ahn; al = aln;
    }

    // epilogue: direct stores to g_xp[t][b][n]; rows m and m+8 share t.
    {
        int m = mt * 128 + warp * 16 + gr;
        int t = m >> 6, b = m & 63;
        float* p0 = g_xp + (size_t)t * (Bq * G4) + (size_t)b * G4 + nt * 128 + tc;
        float* p1 = p0 + 8 * G4;
#pragma unroll
        for (int nf = 0; nf < 16; nf++) {
            *(float2*)&p0[nf * 8] = make_float2(c[nf][0], c[nf][1]);
            *(float2*)&p1[nf * 8] = make_float2(c[nf][2], c[nf][3]);
        }
    }
}

// ---------------------------------------------------------------------------
// smem layout (rec)
// ---------------------------------------------------------------------------
#define OFF_WF_LO 65536
#define OFF_HF    131072
#define OFF_HF_LO 147456
#define OFF_PEX   163840
#define OFF_HO    172544
#define OFF_HBL   173568
#define OFF_BS    174656
#define REC_SMEM  174912

__global__ __launch_bounds__(512, 1) void lstm_rec(
    const float* __restrict__ Whh, const float* __restrict__ bih,
    const float* __restrict__ bhh, float* __restrict__ out)
{
    extern __shared__ __align__(16) char smc[];
    uint2* wfHI = (uint2*)(smc);
    uint2* wfLO = (uint2*)(smc + OFF_WF_LO);
    uint4* hfHI = (uint4*)(smc + OFF_HF);
    uint4* hfLO = (uint4*)(smc + OFF_HF_LO);
    float* pex = (float*)(smc + OFF_PEX);
    float* ho = (float*)(smc + OFF_HO);
    unsigned* hbl = (unsigned*)(smc + OFF_HBL);
    float* bsm = (float*)(smc + OFF_BS);

    const int tid = threadIdx.x;
    const int warp = tid >> 5;
    const int lane = tid & 31;
    const int bq = blockIdx.x >> 5;
    const int hg = blockIdx.x & 31;
    const int b0 = bq * 16;
    const int hc0 = hg * 16;
    const int eb = (tid >> 4) & 15;   // lanes = consecutive hc (coalesced ldg)
    const int ehcl = tid & 15;
    const int nf = warp & 7;
    const int kh = warp >> 3;
    unsigned* cnt = &g_cnt[bq * 32];

    for (int idx = tid; idx < 8192; idx += 512) {
        int l = idx & 31, nfi = (idx >> 5) & 7, kc = idx >> 8;
        int gr = l >> 2, tc2 = (l & 3) * 2;
        int c = nfi * 8 + gr;
        int grow = (c & 3) * 512 + hc0 + (c >> 2);
        const float* wb = Whh + (size_t)grow * 512 + kc * 16 + tc2;
        float2 r0 = *(const float2*)wb;
        float2 r1 = *(const float2*)(wb + 8);
        unsigned h0, l0, h1, l1;
        split2(r0, h0, l0);
        split2(r1, h1, l1);
        wfHI[(kc * 8 + nfi) * 32 + l] = make_uint2(h0, h1);
        wfLO[(kc * 8 + nfi) * 32 + l] = make_uint2(l0, l1);
    }
    if (tid < 64)
        bsm[tid] = bih[(tid & 3) * 512 + hc0 + (tid >> 2)]
                 + bhh[(tid & 3) * 512 + hc0 + (tid >> 2)];
    __syncthreads();

    float cst = 0.f;

#pragma unroll 1
    for (int t = 0; t < Tq; t++) {
        if (tid == 0 && t > 0) {
            unsigned tgt = 32u * (unsigned)t;
            unsigned v;
            do {
                asm volatile("ld.acquire.gpu.u32 %0, [%1];"
                             : "=r"(v) : "l"(cnt) : "memory");
            } while (v < tgt);
        }
        __syncthreads();

        float xv0 = 0.f, xv1 = 0.f, xv2 = 0.f, xv3 = 0.f;
        if (tid < 256) {
            // [t][b][n] layout; lanes read consecutive n (coalesced)
            const float* xpt = g_xp + (size_t)t * (Bq * G4)
                             + (size_t)(b0 + eb) * G4 + hc0 + ehcl;
            xv0 = __ldg(xpt + 0 * 512);
            xv1 = __ldg(xpt + 1 * 512);
            xv2 = __ldg(xpt + 2 * 512);
            xv3 = __ldg(xpt + 3 * 512);
        }

        if (t > 0) {
            const char* gB = (const char*)g_hf + (size_t)(t & 1) * 131072
                           + bq * 16384 + kh * 8192;
            char* sH = (char*)hfHI + kh * 8192;
            char* sL = (char*)hfLO + kh * 8192;
            int l = tid & 255;
            cpa16(sH + l * 16, gB + l * 16);
            cpa16(sH + (l + 256) * 16, gB + (l + 256) * 16);
            cpa16(sL + l * 16, gB + 65536 + l * 16);
            cpa16(sL + (l + 256) * 16, gB + 65536 + (l + 256) * 16);
            cpcommit();
            cpwait<0>();
            asm volatile("bar.sync %0, 256;" :: "r"(1 + kh) : "memory");

            float cc[4] = { 0.f, 0.f, 0.f, 0.f };
#pragma unroll 4
            for (int kc16 = 0; kc16 < 16; kc16++) {
                int kc = kh * 16 + kc16;
                uint4 ah = hfHI[kc * 32 + lane];
                uint4 al = hfLO[kc * 32 + lane];
                uint2 wh = wfHI[(kc * 8 + nf) * 32 + lane];
                uint2 wl = wfLO[(kc * 8 + nf) * 32 + lane];
                mma16816(cc, ah, wh.x, wh.y);
                mma16816(cc, al, wh.x, wh.y);
                mma16816(cc, ah, wl.x, wl.y);
            }
            {
                int gr = lane >> 2, tc2 = (lane & 3) * 2;
                int col = nf * 8 + tc2;
                *(float2*)&pex[(kh * 16 + gr) * 68 + col] = make_float2(cc[0], cc[1]);
                *(float2*)&pex[(kh * 16 + gr + 8) * 68 + col] = make_float2(cc[2], cc[3]);
            }
            __syncthreads();
        }

        if (tid < 256) {
            float g0 = xv0 + bsm[ehcl * 4 + 0];
            float g1 = xv1 + bsm[ehcl * 4 + 1];
            float g2 = xv2 + bsm[ehcl * 4 + 2];
            float g3 = xv3 + bsm[ehcl * 4 + 3];
            if (t > 0) {
                float4 p0 = *(const float4*)&pex[eb * 68 + ehcl * 4];
                float4 p1 = *(const float4*)&pex[(16 + eb) * 68 + ehcl * 4];
                g0 += p0.x + p1.x;
                g1 += p0.y + p1.y;
                g2 += p0.z + p1.z;
                g3 += p0.w + p1.w;
            }
            float iv = sigf(g0);
            float fv = sigf(g1);
            float gv = tanhx(g2);
            float ov = sigf(g3);
            cst = fv * cst + iv * gv;
            float hv = ov * tanhx(cst);

            ho[eb * 16 + ehcl] = hv;
            {
                __nv_bfloat16 hh = __float2bfloat16(hv);
                __nv_bfloat16 hl = __float2bfloat16(hv - __bfloat162float(hh));
                hbl[ehcl * 17 + eb] = (unsigned)__bfloat16_as_ushort(hh)
                                    | ((unsigned)__bfloat16_as_ushort(hl) << 16);
            }
            asm volatile("bar.sync 10, 256;" ::: "memory");

            if (tid < 32) {
                if (t < Tq - 1) {
                    int gr = lane >> 2;
                    int k0 = (lane & 3) * 2;
                    unsigned x0 = hbl[k0 * 17 + gr],        x1 = hbl[(k0 + 1) * 17 + gr];
                    unsigned y0 = hbl[k0 * 17 + gr + 8],    y1 = hbl[(k0 + 1) * 17 + gr + 8];
                    unsigned z0 = hbl[(k0 + 8) * 17 + gr],  z1 = hbl[(k0 + 9) * 17 + gr];
                    unsigned w0 = hbl[(k0 + 8) * 17 + gr + 8], w1 = hbl[(k0 + 9) * 17 + gr + 8];
                    uint4 hi = make_uint4(__byte_perm(x0, x1, 0x5410),
                                          __byte_perm(y0, y1, 0x5410),
                                          __byte_perm(z0, z1, 0x5410),
                                          __byte_perm(w0, w1, 0x5410));
                    uint4 lo = make_uint4(__byte_perm(x0, x1, 0x7632),
                                          __byte_perm(y0, y1, 0x7632),
                                          __byte_perm(z0, z1, 0x7632),
                                          __byte_perm(w0, w1, 0x7632));
                    size_t base = (size_t)((t + 1) & 1) * 8192 + (bq * 32 + hg) * 32 + lane;
                    g_hf[base] = hi;
                    g_hf[base + 4096] = lo;
                    __syncwarp();
                    if (lane == 0) {
                        // RED (no return) on the critical handoff path
                        asm volatile("red.release.gpu.global.add.u32 [%0], 1;"
                                     :: "l"(cnt) : "memory");
                    }
                }
            } else if (tid >= 64 && tid < 128) {
                int row = (tid - 64) >> 2, f4 = (tid - 64) & 3;
                float4 v = ((const float4*)(ho + row * 16))[f4];
                *(float4*)&out[(size_t)t * (Bq * Hq) + (size_t)(b0 + row) * Hq
                               + hc0 + f4 * 4] = v;
            }
        }
    }

    // global finish: last CTA resets cross-launch state (replay-safe)
    if (tid == 0) {
        unsigned old;
        asm volatile("atom.release.gpu.add.u32 %0, [%1], 1;"
                     : "=r"(old) : "l"(&g_fin) : "memory");
        if (old == 127u) {
            for (int i = 0; i < 4; i++) ((volatile unsigned*)g_cnt)[i * 32] = 0u;
            *((volatile unsigned*)&g_fin) = 0u;
        }
    }
}

extern "C" void kernel_launch(void* const* d_in, const int* in_sizes, int n_in,
                              void* d_out, int out_size) {
    const float* x   = (const float*)d_in[0];   // [512,64,512]
    const float* Wih = (const float*)d_in[1];   // [2048,512]
    const float* Whh = (const float*)d_in[2];   // [2048,512]
    const float* bih = (const float*)d_in[3];   // [2048]
    const float* bhh = (const float*)d_in[4];   // [2048]
    float* out = (float*)d_out;                 // [512,64,512]

    cudaFuncSetAttribute(lstm_rec, cudaFuncAttributeMaxDynamicSharedMemorySize, REC_SMEM);
    cudaFuncSetAttribute(gemm_tc, cudaFuncAttributeMaxDynamicSharedMemorySize, GEMM_SMEM);

    conv_a<<<8192, 256>>>(x);
    conv_w<<<1024, 256>>>(Wih);
    gemm_tc<<<dim3(16, 256), 256, GEMM_SMEM>>>();
    lstm_rec<<<128, 512, REC_SMEM>>>(Whh, bih, bhh, out);
}